// round 10
// baseline (speedup 1.0000x reference)
#include <cuda_runtime.h>
#include <cuda_bf16.h>
#include <cstdint>
#include <cstddef>

// Problem constants
#define SEQ    512
#define BATCH  64
#define UNITS  512
#define GATES  2048          // 4*UNITS, Keras order i,f,g,o

// -------------------- device scratch (no cudaMalloc allowed) --------------------
__device__ float g_xpre[(size_t)SEQ * BATCH * GATES];        // [t][b][gate_col]
__device__ __nv_bfloat16 g_hh[2][BATCH * UNITS];             // h hi, double buffered
__device__ __nv_bfloat16 g_hl[2][BATCH * UNITS];             // h lo
__device__ unsigned g_flag[4][32];                           // per-bg line of 32 CTA counters

// -------------------- helpers --------------------
__device__ __forceinline__ uint32_t f32_to_tf32(float x) {
    uint32_t r; asm("cvt.rna.tf32.f32 %0, %1;" : "=r"(r) : "f"(x)); return r;
}

__device__ __forceinline__ void mma_tf32(float c[4],
                                         uint32_t a0, uint32_t a1, uint32_t a2, uint32_t a3,
                                         uint32_t b0, uint32_t b1) {
    asm volatile(
        "mma.sync.aligned.m16n8k8.row.col.f32.tf32.tf32.f32 "
        "{%0,%1,%2,%3}, {%4,%5,%6,%7}, {%8,%9}, {%0,%1,%2,%3};"
        : "+f"(c[0]), "+f"(c[1]), "+f"(c[2]), "+f"(c[3])
        : "r"(a0), "r"(a1), "r"(a2), "r"(a3), "r"(b0), "r"(b1));
}

__device__ __forceinline__ void mma_bf16(float c[4],
                                         uint32_t a0, uint32_t a1, uint32_t a2, uint32_t a3,
                                         uint32_t b0, uint32_t b1) {
    asm volatile(
        "mma.sync.aligned.m16n8k16.row.col.f32.bf16.bf16.f32 "
        "{%0,%1,%2,%3}, {%4,%5,%6,%7}, {%8,%9}, {%0,%1,%2,%3};"
        : "+f"(c[0]), "+f"(c[1]), "+f"(c[2]), "+f"(c[3])
        : "r"(a0), "r"(a1), "r"(a2), "r"(a3), "r"(b0), "r"(b1));
}

__device__ __forceinline__ uint32_t packbf(__nv_bfloat16 lo, __nv_bfloat16 hi) {
    __nv_bfloat162 p = __halves2bfloat162(lo, hi);   // .x = low 16 bits (even k)
    return *(uint32_t*)&p;
}

__device__ __forceinline__ float sigmoid_f(float x) {
    return 1.0f / (1.0f + __expf(-x));
}
__device__ __forceinline__ float tanh_f(float x) {
    float e = __expf(-2.0f * fabsf(x));
    float t = (1.0f - e) / (1.0f + e);
    return copysignf(t, x);
}

// -------------------- kernel 1: Xpre = x @ Wx + bias (mma.sync tf32) --------------------
// Output layout: time-major g_xpre[t][b][col]. Register-prefetch double buffer.
#define A_PITCH 36
#define B_PITCH 136

__global__ __launch_bounds__(256, 2) void xpre_mma(
    const float* __restrict__ X,     // [32768, 512] rows m = b*512 + t
    const float* __restrict__ Wx,    // [512, 2048]
    const float* __restrict__ bias)  // [2048]
{
    __shared__ uint32_t sA[128 * A_PITCH];   // 18 KB
    __shared__ uint32_t sB[32 * B_PITCH];    // 17.4 KB

    const int tid  = threadIdx.x;
    const int lane = tid & 31;
    const int wid  = tid >> 5;
    const int m0 = blockIdx.y << 7;
    const int n0 = blockIdx.x << 7;
    const int wr = wid >> 1;
    const int wc = wid & 1;
    const int gid = lane >> 2;
    const int tig = lane & 3;

    int a_row[4], a_c4[4], b_k[4], b_c4[4];
#pragma unroll
    for (int it = 0; it < 4; it++) {
        int idx = tid + (it << 8);
        a_row[it] = idx >> 3;
        a_c4[it]  = (idx & 7) << 2;
        b_k[it]   = idx >> 5;
        b_c4[it]  = (idx & 31) << 2;
    }

    float acc[2][8][4];
#pragma unroll
    for (int mf = 0; mf < 2; mf++)
#pragma unroll
        for (int nf = 0; nf < 8; nf++)
#pragma unroll
            for (int q = 0; q < 4; q++) acc[mf][nf][q] = 0.0f;

    float4 pa[4], pb[4];
#pragma unroll
    for (int it = 0; it < 4; it++) {
        pa[it] = *(const float4*)(X + (size_t)(m0 + a_row[it]) * 512 + a_c4[it]);
        pb[it] = *(const float4*)(Wx + (size_t)b_k[it] * 2048 + n0 + b_c4[it]);
    }

    for (int kc = 0; kc < 16; kc++) {
#pragma unroll
        for (int it = 0; it < 4; it++) {
            uint4 t;
            t.x = f32_to_tf32(pa[it].x); t.y = f32_to_tf32(pa[it].y);
            t.z = f32_to_tf32(pa[it].z); t.w = f32_to_tf32(pa[it].w);
            *(uint4*)&sA[a_row[it] * A_PITCH + a_c4[it]] = t;
            uint4 u;
            u.x = f32_to_tf32(pb[it].x); u.y = f32_to_tf32(pb[it].y);
            u.z = f32_to_tf32(pb[it].z); u.w = f32_to_tf32(pb[it].w);
            *(uint4*)&sB[b_k[it] * B_PITCH + b_c4[it]] = u;
        }
        __syncthreads();

        if (kc < 15) {
            const int k0n = (kc + 1) << 5;
#pragma unroll
            for (int it = 0; it < 4; it++) {
                pa[it] = *(const float4*)(X + (size_t)(m0 + a_row[it]) * 512 + k0n + a_c4[it]);
                pb[it] = *(const float4*)(Wx + (size_t)(k0n + b_k[it]) * 2048 + n0 + b_c4[it]);
            }
        }

#pragma unroll
        for (int k8 = 0; k8 < 4; k8++) {
            const int kb = k8 << 3;
            uint32_t a[2][4];
#pragma unroll
            for (int mf = 0; mf < 2; mf++) {
                int r = wr * 32 + mf * 16 + gid;
                a[mf][0] = sA[r * A_PITCH + kb + tig];
                a[mf][1] = sA[(r + 8) * A_PITCH + kb + tig];
                a[mf][2] = sA[r * A_PITCH + kb + tig + 4];
                a[mf][3] = sA[(r + 8) * A_PITCH + kb + tig + 4];
            }
#pragma unroll
            for (int nf = 0; nf < 8; nf++) {
                int n = wc * 64 + nf * 8 + gid;
                uint32_t b0 = sB[(kb + tig) * B_PITCH + n];
                uint32_t b1 = sB[(kb + tig + 4) * B_PITCH + n];
                mma_tf32(acc[0][nf], a[0][0], a[0][1], a[0][2], a[0][3], b0, b1);
                mma_tf32(acc[1][nf], a[1][0], a[1][1], a[1][2], a[1][3], b0, b1);
            }
        }
        __syncthreads();
    }

    const int bidx = m0 >> 9;
#pragma unroll
    for (int nf = 0; nf < 8; nf++) {
        int col = n0 + wc * 64 + nf * 8 + tig * 2;
        float bv0 = bias[col], bv1 = bias[col + 1];
#pragma unroll
        for (int mf = 0; mf < 2; mf++) {
            int r0 = m0 + wr * 32 + mf * 16 + gid;
            int t0 = r0 & 511;
            float2 lo = make_float2(acc[mf][nf][0] + bv0, acc[mf][nf][1] + bv1);
            float2 hi = make_float2(acc[mf][nf][2] + bv0, acc[mf][nf][3] + bv1);
            *(float2*)&g_xpre[((size_t)t0 * 64 + bidx) * 2048 + col]       = lo;
            *(float2*)&g_xpre[((size_t)(t0 + 8) * 64 + bidx) * 2048 + col] = hi;
        }
    }
}

// -------------------- kernel 2: persistent LSTM recurrence --------------------
// 128 CTAs = 4 bg (16 batches) x 32 ug (16 units). 512 threads, 16 warps:
// warp w -> K-octant (w&7, 64 k's) x gate-half (w>>3, n=32 cols).
// 3 split-products chained into ONE accumulator per n8 tile (4 indep chains).
// Partials in sZp[8][1024]; elementwise threads fold 8 partials + Xpre regs.
#define NTHR 512
#define WP  68            // sW pitch (uint2)
#define HPP 260           // sHh/sHl pitch (uint32)
#define SW_BYTES (256 * WP * 8)
#define SH_BYTES (16 * HPP * 4)
#define SMEM_BYTES (SW_BYTES + 2 * SH_BYTES + 8 * 1024 * 4)

__global__ __launch_bounds__(NTHR, 1) void lstm_seq7(
    const float* __restrict__ h0g,  // [64, 512]
    const float* __restrict__ c0,   // [64, 512]
    const float* __restrict__ Wh,   // [512, 2048]
    float* __restrict__ out)        // [512, 64, 512]
{
    extern __shared__ char smraw[];
    uint2*    sW  = (uint2*)smraw;                       // [kp 256][c 64] (+pad)
    uint32_t* sHh = (uint32_t*)(smraw + SW_BYTES);       // [row 16][kp 256] (+pad)
    uint32_t* sHl = sHh + 16 * HPP;
    float*    sZp = (float*)(smraw + SW_BYTES + 2 * SH_BYTES);  // [8][gate][16b][16u]

    const int tid  = threadIdx.x;
    const int lane = tid & 31;
    const int wid  = tid >> 5;
    const int ug = blockIdx.x & 31;      // unit group
    const int bg = blockIdx.x >> 5;      // batch group
    const int u0 = ug << 4;
    const int b0 = bg << 4;

    // ---- one-time: split Wh slice into smem (hi,lo) packed words
    for (int idx = tid; idx < 16384; idx += NTHR) {
        int kp = idx >> 6;               // 0..255 (pairs of k)
        int c  = idx & 63;               // gate*16 + j
        int gate = c >> 4, j = c & 15;
        int col = gate * 512 + u0 + j;
        float w0 = Wh[(size_t)(2 * kp) * 2048 + col];
        float w1 = Wh[(size_t)(2 * kp + 1) * 2048 + col];
        __nv_bfloat16 h0b = __float2bfloat16_rn(w0);
        __nv_bfloat16 h1b = __float2bfloat16_rn(w1);
        __nv_bfloat16 l0b = __float2bfloat16_rn(w0 - __bfloat162float(h0b));
        __nv_bfloat16 l1b = __float2bfloat16_rn(w1 - __bfloat162float(h1b));
        sW[kp * WP + c] = make_uint2(packbf(h0b, h1b), packbf(l0b, l1b));
    }

    // ---- per-thread cell state + initial h split (threads 0-255 own a (b,u))
    const int bl = (tid & 255) >> 4, ul = tid & 15;
    const int gidx = (b0 + bl) * 512 + u0 + ul;
    float c_reg = 0.0f;
    if (tid < 256) {
        c_reg = c0[gidx];
        float hv0 = h0g[gidx];
        __nv_bfloat16 hi = __float2bfloat16_rn(hv0);
        g_hh[0][gidx] = hi;
        g_hl[0][gidx] = __float2bfloat16_rn(hv0 - __bfloat162float(hi));
    }

    // ---- warp roles: K-octant = wid&7 (32 kp), gate-half = wid>>3 (32 cols)
    const int kq = wid & 7;
    const int gh = wid >> 3;
    const int g  = lane >> 2;            // 0..7
    const int t4 = lane & 3;             // 0..3
    const int kpBase = kq << 5;          // 32 k-pairs = 64 k's
    const uint32_t* Ah  = sHh + g * HPP + kpBase;
    const uint32_t* Ah8 = sHh + (g + 8) * HPP + kpBase;
    const uint32_t* Al  = sHl + g * HPP + kpBase;
    const uint32_t* Al8 = sHl + (g + 8) * HPP + kpBase;
    const uint2* Bg = sW + (size_t)kpBase * WP + (gh * 32 + g);
    float* sZme = sZp + kq * 1024;

    // ---- per-thread Xpre prefetch (threads 0-255; 4 gate values), t=0
    const float* xbase = g_xpre + (size_t)(b0 + bl) * 2048 + u0 + ul;
    float xv0 = 0.f, xv1 = 0.f, xv2 = 0.f, xv3 = 0.f;
    if (tid < 256) {
        xv0 = xbase[0];
        xv1 = xbase[512];
        xv2 = xbase[1024];
        xv3 = xbase[1536];
    }

    // ---- publish init state (release atomic; monotonic, replay-safe)
    __syncthreads();
    if (wid == 0 && lane == 0) {
        unsigned n;
        asm volatile("atom.release.gpu.global.add.u32 %0, [%1], %2;"
                     : "=r"(n) : "l"(&g_flag[bg][ug]), "r"(1u) : "memory");
    }

    for (int tstep = 0; tstep < SEQ; tstep++) {
        const int rb = tstep & 1;

        // ---- WAIT: warp 0 polls 32 peer flags vs our own (monotonic equality)
        if (wid == 0) {
            unsigned own;
            asm volatile("ld.acquire.gpu.global.u32 %0, [%1];"
                         : "=r"(own) : "l"(&g_flag[bg][ug]) : "memory");
            for (;;) {
                unsigned v;
                asm volatile("ld.acquire.gpu.global.u32 %0, [%1];"
                             : "=r"(v) : "l"(&g_flag[bg][lane]) : "memory");
                if (__all_sync(0xffffffffu, (int)(v - own) >= 0)) break;
            }
        }
        __syncthreads();

        // ---- PHASE 1: copy pre-split H tile into smem (all 16 warps)
        {
            const uint4* srcHh = (const uint4*)(g_hh[rb] + (size_t)b0 * 512);
            const uint4* srcHl = (const uint4*)(g_hl[rb] + (size_t)b0 * 512);
#pragma unroll
            for (int it = 0; it < 2; it++) {
                int i = tid + (it << 9);        // 0..1023
                int row = i >> 6, q = i & 63;
                *(uint4*)&sHh[row * HPP + q * 4] = srcHh[row * 64 + q];
                *(uint4*)&sHl[row * HPP + q * 4] = srcHl[row * 64 + q];
            }
        }
        __syncthreads();

        // ---- PHASE 2: GEMM, all 16 warps (bf16 3-term split, chained accum)
        {
            float acc[4][4];
#pragma unroll
            for (int j = 0; j < 4; j++)
#pragma unroll
                for (int q = 0; q < 4; q++) acc[j][q] = 0.0f;

#pragma unroll
            for (int kb = 0; kb < 4; kb++) {
                int wa = kb * 8 + t4;
                uint32_t ah0 = Ah[wa],  ah1 = Ah8[wa];
                uint32_t ah2 = Ah[wa + 4], ah3 = Ah8[wa + 4];
                uint32_t al0 = Al[wa],  al1 = Al8[wa];
                uint32_t al2 = Al[wa + 4], al3 = Al8[wa + 4];
#pragma unroll
                for (int j = 0; j < 4; j++) {
                    uint2 B0 = Bg[(size_t)wa * WP + j * 8];
                    uint2 B1 = Bg[(size_t)(wa + 4) * WP + j * 8];
                    mma_bf16(acc[j], ah0, ah1, ah2, ah3, B0.x, B1.x);  // h_hi @ W_hi
                    mma_bf16(acc[j], ah0, ah1, ah2, ah3, B0.y, B1.y);  // h_hi @ W_lo
                    mma_bf16(acc[j], al0, al1, al2, al3, B0.x, B1.x);  // h_lo @ W_hi
                }
            }

            // partial stores (disjoint per warp within its sZp bank)
#pragma unroll
            for (int j = 0; j < 4; j++) {
                int cb = gh * 32 + j * 8 + 2 * t4;   // col 0..63
                int gate = cb >> 4, u = cb & 15;
                int o0 = gate * 256 + g * 16 + u;
                int o1 = gate * 256 + (g + 8) * 16 + u;
                *(float2*)&sZme[o0] = make_float2(acc[j][0], acc[j][1]);
                *(float2*)&sZme[o1] = make_float2(acc[j][2], acc[j][3]);
            }
        }
        __syncthreads();

        // ---- PHASE 3: elementwise LSTM cell (threads 0-255)
        float hv = 0.0f;
        if (tid < 256) {
            int o = bl * 16 + ul;
            float zi = xv0, zf = xv1, zg = xv2, zo = xv3;
#pragma unroll
            for (int q = 0; q < 8; q++) {
                const float* p = sZp + q * 1024 + o;
                zi += p[0];
                zf += p[256];
                zg += p[512];
                zo += p[768];
            }
            float ig = sigmoid_f(zi);
            float fg = sigmoid_f(zf);
            float gg = tanh_f(zg);
            float og = sigmoid_f(zo);
            c_reg = fg * c_reg + ig * gg;
            hv = og * tanh_f(c_reg);
            __nv_bfloat16 hi = __float2bfloat16_rn(hv);
            g_hh[rb ^ 1][gidx] = hi;
            g_hl[rb ^ 1][gidx] = __float2bfloat16_rn(hv - __bfloat162float(hi));
        }
        // prefetch next step's Xpre (independent)
        if (tid < 256 && tstep + 1 < SEQ) {
            const float* xnext = xbase + (size_t)(tstep + 1) * 64 * 2048;
            xv0 = xnext[0];
            xv1 = xnext[512];
            xv2 = xnext[1024];
            xv3 = xnext[1536];
        }
        __syncthreads();

        // ---- ARRIVE (release atomic), then out store off the critical path
        if (wid == 0 && lane == 0) {
            unsigned n;
            asm volatile("atom.release.gpu.global.add.u32 %0, [%1], %2;"
                         : "=r"(n) : "l"(&g_flag[bg][ug]), "r"(1u) : "memory");
        }
        if (tid < 256) {
            out[((size_t)tstep * 64 + b0 + bl) * 512 + u0 + ul] = hv;
        }
    }
}

// -------------------- launch --------------------
// Input order (metadata): x [64,512,512], h0 [64,512], c0 [64,512],
//                         Wx [512,2048], Wh [512,2048], b [2048]
extern "C" void kernel_launch(void* const* d_in, const int* in_sizes, int n_in,
                              void* d_out, int out_size) {
    const float* x    = (const float*)d_in[0];
    const float* h0   = (const float*)d_in[1];
    const float* c0   = (const float*)d_in[2];
    const float* Wx   = (const float*)d_in[3];
    const float* Wh   = (const float*)d_in[4];
    const float* bias = (const float*)d_in[5];
    float* out = (float*)d_out;

    cudaFuncSetAttribute(lstm_seq7, cudaFuncAttributeMaxDynamicSharedMemorySize, SMEM_BYTES);

    xpre_mma<<<dim3(16, 256), 256>>>(x, Wx, bias);
    lstm_seq7<<<128, NTHR, SMEM_BYTES>>>(h0, c0, Wh, out);
}

// round 11
// speedup vs baseline: 1.0389x; 1.0389x over previous
#include <cuda_runtime.h>
#include <cuda_bf16.h>
#include <cstdint>
#include <cstddef>

// Problem constants
#define SEQ    512
#define BATCH  64
#define UNITS  512
#define GATES  2048          // 4*UNITS, Keras order i,f,g,o

// -------------------- device scratch (no cudaMalloc allowed) --------------------
__device__ float g_xpre[(size_t)SEQ * BATCH * GATES];        // [t][b][gate_col]
__device__ __nv_bfloat16 g_hh[2][BATCH * UNITS];             // h hi, double buffered
__device__ __nv_bfloat16 g_hl[2][BATCH * UNITS];             // h lo
__device__ unsigned g_hflag[4][32];                          // [bg][ug] monotonic producer flags

// -------------------- helpers --------------------
__device__ __forceinline__ uint32_t f32_to_tf32(float x) {
    uint32_t r; asm("cvt.rna.tf32.f32 %0, %1;" : "=r"(r) : "f"(x)); return r;
}

__device__ __forceinline__ void mma_tf32(float c[4],
                                         uint32_t a0, uint32_t a1, uint32_t a2, uint32_t a3,
                                         uint32_t b0, uint32_t b1) {
    asm volatile(
        "mma.sync.aligned.m16n8k8.row.col.f32.tf32.tf32.f32 "
        "{%0,%1,%2,%3}, {%4,%5,%6,%7}, {%8,%9}, {%0,%1,%2,%3};"
        : "+f"(c[0]), "+f"(c[1]), "+f"(c[2]), "+f"(c[3])
        : "r"(a0), "r"(a1), "r"(a2), "r"(a3), "r"(b0), "r"(b1));
}

__device__ __forceinline__ void mma_bf16(float c[4],
                                         uint32_t a0, uint32_t a1, uint32_t a2, uint32_t a3,
                                         uint32_t b0, uint32_t b1) {
    asm volatile(
        "mma.sync.aligned.m16n8k16.row.col.f32.bf16.bf16.f32 "
        "{%0,%1,%2,%3}, {%4,%5,%6,%7}, {%8,%9}, {%0,%1,%2,%3};"
        : "+f"(c[0]), "+f"(c[1]), "+f"(c[2]), "+f"(c[3])
        : "r"(a0), "r"(a1), "r"(a2), "r"(a3), "r"(b0), "r"(b1));
}

__device__ __forceinline__ uint32_t packbf(__nv_bfloat16 lo, __nv_bfloat16 hi) {
    __nv_bfloat162 p = __halves2bfloat162(lo, hi);   // .x = low 16 bits (even k)
    return *(uint32_t*)&p;
}

__device__ __forceinline__ float sigmoid_f(float x) {
    return 1.0f / (1.0f + __expf(-x));
}
__device__ __forceinline__ float tanh_f(float x) {
    float e = __expf(-2.0f * fabsf(x));
    float t = (1.0f - e) / (1.0f + e);
    return copysignf(t, x);
}

// -------------------- kernel 1: Xpre = x @ Wx + bias (mma.sync tf32) --------------------
// Output layout: time-major g_xpre[t][b][col]. Register-prefetch double buffer.
#define A_PITCH 36
#define B_PITCH 136

__global__ __launch_bounds__(256, 2) void xpre_mma(
    const float* __restrict__ X,     // [32768, 512] rows m = b*512 + t
    const float* __restrict__ Wx,    // [512, 2048]
    const float* __restrict__ bias)  // [2048]
{
    __shared__ uint32_t sA[128 * A_PITCH];   // 18 KB
    __shared__ uint32_t sB[32 * B_PITCH];    // 17.4 KB

    const int tid  = threadIdx.x;
    const int lane = tid & 31;
    const int wid  = tid >> 5;
    const int m0 = blockIdx.y << 7;
    const int n0 = blockIdx.x << 7;
    const int wr = wid >> 1;
    const int wc = wid & 1;
    const int gid = lane >> 2;
    const int tig = lane & 3;

    int a_row[4], a_c4[4], b_k[4], b_c4[4];
#pragma unroll
    for (int it = 0; it < 4; it++) {
        int idx = tid + (it << 8);
        a_row[it] = idx >> 3;
        a_c4[it]  = (idx & 7) << 2;
        b_k[it]   = idx >> 5;
        b_c4[it]  = (idx & 31) << 2;
    }

    float acc[2][8][4];
#pragma unroll
    for (int mf = 0; mf < 2; mf++)
#pragma unroll
        for (int nf = 0; nf < 8; nf++)
#pragma unroll
            for (int q = 0; q < 4; q++) acc[mf][nf][q] = 0.0f;

    float4 pa[4], pb[4];
#pragma unroll
    for (int it = 0; it < 4; it++) {
        pa[it] = *(const float4*)(X + (size_t)(m0 + a_row[it]) * 512 + a_c4[it]);
        pb[it] = *(const float4*)(Wx + (size_t)b_k[it] * 2048 + n0 + b_c4[it]);
    }

    for (int kc = 0; kc < 16; kc++) {
#pragma unroll
        for (int it = 0; it < 4; it++) {
            uint4 t;
            t.x = f32_to_tf32(pa[it].x); t.y = f32_to_tf32(pa[it].y);
            t.z = f32_to_tf32(pa[it].z); t.w = f32_to_tf32(pa[it].w);
            *(uint4*)&sA[a_row[it] * A_PITCH + a_c4[it]] = t;
            uint4 u;
            u.x = f32_to_tf32(pb[it].x); u.y = f32_to_tf32(pb[it].y);
            u.z = f32_to_tf32(pb[it].z); u.w = f32_to_tf32(pb[it].w);
            *(uint4*)&sB[b_k[it] * B_PITCH + b_c4[it]] = u;
        }
        __syncthreads();

        if (kc < 15) {
            const int k0n = (kc + 1) << 5;
#pragma unroll
            for (int it = 0; it < 4; it++) {
                pa[it] = *(const float4*)(X + (size_t)(m0 + a_row[it]) * 512 + k0n + a_c4[it]);
                pb[it] = *(const float4*)(Wx + (size_t)(k0n + b_k[it]) * 2048 + n0 + b_c4[it]);
            }
        }

#pragma unroll
        for (int k8 = 0; k8 < 4; k8++) {
            const int kb = k8 << 3;
            uint32_t a[2][4];
#pragma unroll
            for (int mf = 0; mf < 2; mf++) {
                int r = wr * 32 + mf * 16 + gid;
                a[mf][0] = sA[r * A_PITCH + kb + tig];
                a[mf][1] = sA[(r + 8) * A_PITCH + kb + tig];
                a[mf][2] = sA[r * A_PITCH + kb + tig + 4];
                a[mf][3] = sA[(r + 8) * A_PITCH + kb + tig + 4];
            }
#pragma unroll
            for (int nf = 0; nf < 8; nf++) {
                int n = wc * 64 + nf * 8 + gid;
                uint32_t b0 = sB[(kb + tig) * B_PITCH + n];
                uint32_t b1 = sB[(kb + tig + 4) * B_PITCH + n];
                mma_tf32(acc[0][nf], a[0][0], a[0][1], a[0][2], a[0][3], b0, b1);
                mma_tf32(acc[1][nf], a[1][0], a[1][1], a[1][2], a[1][3], b0, b1);
            }
        }
        __syncthreads();
    }

    const int bidx = m0 >> 9;
#pragma unroll
    for (int nf = 0; nf < 8; nf++) {
        int col = n0 + wc * 64 + nf * 8 + tig * 2;
        float bv0 = bias[col], bv1 = bias[col + 1];
#pragma unroll
        for (int mf = 0; mf < 2; mf++) {
            int r0 = m0 + wr * 32 + mf * 16 + gid;
            int t0 = r0 & 511;
            float2 lo = make_float2(acc[mf][nf][0] + bv0, acc[mf][nf][1] + bv1);
            float2 hi = make_float2(acc[mf][nf][2] + bv0, acc[mf][nf][3] + bv1);
            *(float2*)&g_xpre[((size_t)t0 * 64 + bidx) * 2048 + col]       = lo;
            *(float2*)&g_xpre[((size_t)(t0 + 8) * 64 + bidx) * 2048 + col] = hi;
        }
    }
}

// -------------------- kernel 2: persistent LSTM, fine-grained dataflow --------------------
// 128 CTAs = 4 bg (16 batches) x 32 ug (16 units). 512 threads, 16 warps:
// warp (kq = wid&7, gh = wid>>3). Warp kq depends only on producer CTAs
// ug in [4kq, 4kq+4): it polls those 4 flags, then loads its A fragments
// DIRECTLY from global (8x LDG.128, kp-permuted; B reads permuted to match).
// No H smem staging. Partials to sZp[8][1024]; fold threads (tid<256) finish.
#define NTHR 512
#define WP   65                       // sW pitch in uint2 (conflict-free for new B pattern)
#define SW_BYTES (256 * WP * 8)       // 133120
#define SMEM_BYTES (SW_BYTES + 8 * 1024 * 4 + 16)

__global__ __launch_bounds__(NTHR, 1) void lstm_seq8(
    const float* __restrict__ h0g,  // [64, 512]
    const float* __restrict__ c0,   // [64, 512]
    const float* __restrict__ Wh,   // [512, 2048]
    float* __restrict__ out)        // [512, 64, 512]
{
    extern __shared__ char smraw[];
    uint2*    sW  = (uint2*)smraw;                       // [kp 0..255][c 0..63] pitch WP
    float*    sZp = (float*)(smraw + SW_BYTES);          // [8][gate][16b][16u]
    unsigned* sF0 = (unsigned*)(smraw + SW_BYTES + 8 * 1024 * 4);

    const int tid  = threadIdx.x;
    const int lane = tid & 31;
    const int wid  = tid >> 5;
    const int ug = blockIdx.x & 31;      // unit group
    const int bg = blockIdx.x >> 5;      // batch group
    const int u0 = ug << 4;
    const int b0 = bg << 4;

    // ---- read launch-base flag value (own flag; only we write it) ----
    if (tid == 0) *sF0 = g_hflag[bg][ug];

    // ---- one-time: split Wh slice into smem (hi,lo) packed words
    for (int idx = tid; idx < 16384; idx += NTHR) {
        int kp = idx >> 6;               // 0..255 (pairs of h-units)
        int c  = idx & 63;               // gate*16 + j
        int gate = c >> 4, j = c & 15;
        int col = gate * 512 + u0 + j;
        float w0 = Wh[(size_t)(2 * kp) * 2048 + col];
        float w1 = Wh[(size_t)(2 * kp + 1) * 2048 + col];
        __nv_bfloat16 h0b = __float2bfloat16_rn(w0);
        __nv_bfloat16 h1b = __float2bfloat16_rn(w1);
        __nv_bfloat16 l0b = __float2bfloat16_rn(w0 - __bfloat162float(h0b));
        __nv_bfloat16 l1b = __float2bfloat16_rn(w1 - __bfloat162float(h1b));
        sW[kp * WP + c] = make_uint2(packbf(h0b, h1b), packbf(l0b, l1b));
    }

    // ---- per-thread cell state + initial h split (threads 0-255 own a (b,u))
    const int bl = (tid & 255) >> 4, ul = tid & 15;
    const int gidx = (b0 + bl) * 512 + u0 + ul;
    float c_reg = 0.0f;
    if (tid < 256) {
        c_reg = c0[gidx];
        float hv0 = h0g[gidx];
        __nv_bfloat16 hi = __float2bfloat16_rn(hv0);
        g_hh[0][gidx] = hi;
        g_hl[0][gidx] = __float2bfloat16_rn(hv0 - __bfloat162float(hi));
    }

    // ---- warp roles
    const int kq = wid & 7;              // K-octant (64 h-units)
    const int gh = wid >> 3;             // gate-half (32 cols)
    const int g  = lane >> 2;            // 0..7
    const int t4 = lane & 3;             // 0..3
    float* sZme = sZp + kq * 1024;
    const unsigned* pfl = &g_hflag[bg][(kq << 2) | (lane & 3)];   // producer flags
    const uint2* BgBase = sW + (gh * 32 + g);

    // ---- per-thread Xpre prefetch (threads 0-255; 4 gate values), t=0
    const float* xbase = g_xpre + (size_t)(b0 + bl) * 2048 + u0 + ul;
    float xv0 = 0.f, xv1 = 0.f, xv2 = 0.f, xv3 = 0.f;
    if (tid < 256) {
        xv0 = xbase[0];
        xv1 = xbase[512];
        xv2 = xbase[1024];
        xv3 = xbase[1536];
    }

    __syncthreads();
    const unsigned F0 = *sF0;

    // ---- publish h0 (release atomic; monotonic, replay-safe)
    if (tid == 0) {
        unsigned n;
        asm volatile("atom.release.gpu.global.add.u32 %0, [%1], %2;"
                     : "=r"(n) : "l"(&g_hflag[bg][ug]), "r"(1u) : "memory");
    }

    for (int tstep = 0; tstep < SEQ; tstep++) {
        const int rb = tstep & 1;
        const unsigned tgt = F0 + 1 + (unsigned)tstep;

        // ---- per-warp WAIT on this octant's 4 producers
        {
            for (;;) {
                unsigned v;
                asm volatile("ld.acquire.gpu.global.u32 %0, [%1];"
                             : "=r"(v) : "l"(pfl) : "memory");
                if (__all_sync(0xffffffffu, (int)(v - tgt) >= 0)) break;
            }
        }

        // ---- A fragments direct from global (kp-permuted LDG.128)
        // thread (g,t4): rows b0+g, b0+g+8; units kq*64 + blk*32 + t4*8 .. +7
        const __nv_bfloat16* hb = g_hh[rb];
        const __nv_bfloat16* lb = g_hl[rb];
        const size_t rg  = (size_t)(b0 + g) * 512 + kq * 64 + t4 * 8;
        const size_t rg8 = (size_t)(b0 + g + 8) * 512 + kq * 64 + t4 * 8;
        uint4 AH00 = *(const uint4*)(hb + rg);
        uint4 AH01 = *(const uint4*)(hb + rg + 32);
        uint4 AH10 = *(const uint4*)(hb + rg8);
        uint4 AH11 = *(const uint4*)(hb + rg8 + 32);
        uint4 AL00 = *(const uint4*)(lb + rg);
        uint4 AL01 = *(const uint4*)(lb + rg + 32);
        uint4 AL10 = *(const uint4*)(lb + rg8);
        uint4 AL11 = *(const uint4*)(lb + rg8 + 32);

        // ---- GEMM: 48 mma (2 blk x 2 kj x 4 jj x 3 split-products)
        float acc[4][4];
#pragma unroll
        for (int jj = 0; jj < 4; jj++)
#pragma unroll
            for (int q = 0; q < 4; q++) acc[jj][q] = 0.0f;

#pragma unroll
        for (int blk = 0; blk < 2; blk++) {
            const uint32_t* ph0 = (const uint32_t*)(blk ? &AH01 : &AH00);
            const uint32_t* ph1 = (const uint32_t*)(blk ? &AH11 : &AH10);
            const uint32_t* pl0 = (const uint32_t*)(blk ? &AL01 : &AL00);
            const uint32_t* pl1 = (const uint32_t*)(blk ? &AL11 : &AL10);
            const int kpB = kq * 32 + blk * 16 + 4 * t4;
#pragma unroll
            for (int kj = 0; kj < 2; kj++) {
                uint32_t h0 = ph0[kj], h1 = ph1[kj], h2 = ph0[kj + 2], h3 = ph1[kj + 2];
                uint32_t l0 = pl0[kj], l1 = pl1[kj], l2 = pl0[kj + 2], l3 = pl1[kj + 2];
                const uint2* B0p = BgBase + (size_t)(kpB + kj) * WP;
                const uint2* B1p = BgBase + (size_t)(kpB + kj + 2) * WP;
#pragma unroll
                for (int jj = 0; jj < 4; jj++) {
                    uint2 B0 = B0p[jj * 8];
                    uint2 B1 = B1p[jj * 8];
                    mma_bf16(acc[jj], h0, h1, h2, h3, B0.x, B1.x);   // h_hi @ W_hi
                    mma_bf16(acc[jj], h0, h1, h2, h3, B0.y, B1.y);   // h_hi @ W_lo
                    mma_bf16(acc[jj], l0, l1, l2, l3, B0.x, B1.x);   // h_lo @ W_hi
                }
            }
        }

        // ---- partial stores (disjoint per warp within its sZp bank)
#pragma unroll
        for (int jj = 0; jj < 4; jj++) {
            int cb = gh * 32 + jj * 8 + 2 * t4;   // col 0..63
            int gate = cb >> 4, u = cb & 15;
            int o0 = gate * 256 + g * 16 + u;
            int o1 = gate * 256 + (g + 8) * 16 + u;
            *(float2*)&sZme[o0] = make_float2(acc[jj][0], acc[jj][1]);
            *(float2*)&sZme[o1] = make_float2(acc[jj][2], acc[jj][3]);
        }
        __syncthreads();

        // ---- fold + elementwise LSTM cell (threads 0-255)
        float hv = 0.0f;
        if (tid < 256) {
            int o = bl * 16 + ul;
            float zi = xv0, zf = xv1, zg = xv2, zo = xv3;
#pragma unroll
            for (int q = 0; q < 8; q++) {
                const float* p = sZp + q * 1024 + o;
                zi += p[0];
                zf += p[256];
                zg += p[512];
                zo += p[768];
            }
            float ig = sigmoid_f(zi);
            float fg = sigmoid_f(zf);
            float gg = tanh_f(zg);
            float og = sigmoid_f(zo);
            c_reg = fg * c_reg + ig * gg;
            hv = og * tanh_f(c_reg);
            __nv_bfloat16 hi = __float2bfloat16_rn(hv);
            g_hh[rb ^ 1][gidx] = hi;
            g_hl[rb ^ 1][gidx] = __float2bfloat16_rn(hv - __bfloat162float(hi));
        }
        // prefetch next step's Xpre (independent)
        if (tid < 256 && tstep + 1 < SEQ) {
            const float* xnext = xbase + (size_t)(tstep + 1) * 64 * 2048;
            xv0 = xnext[0];
            xv1 = xnext[512];
            xv2 = xnext[1024];
            xv3 = xnext[1536];
        }
        __syncthreads();

        // ---- publish h(t+1) (release atomic), then out store off critical path
        if (tid == 0) {
            unsigned n;
            asm volatile("atom.release.gpu.global.add.u32 %0, [%1], %2;"
                         : "=r"(n) : "l"(&g_hflag[bg][ug]), "r"(1u) : "memory");
        }
        if (tid < 256) {
            out[((size_t)tstep * 64 + b0 + bl) * 512 + u0 + ul] = hv;
        }
    }
}

// -------------------- launch --------------------
// Input order (metadata): x [64,512,512], h0 [64,512], c0 [64,512],
//                         Wx [512,2048], Wh [512,2048], b [2048]
extern "C" void kernel_launch(void* const* d_in, const int* in_sizes, int n_in,
                              void* d_out, int out_size) {
    const float* x    = (const float*)d_in[0];
    const float* h0   = (const float*)d_in[1];
    const float* c0   = (const float*)d_in[2];
    const float* Wx   = (const float*)d_in[3];
    const float* Wh   = (const float*)d_in[4];
    const float* bias = (const float*)d_in[5];
    float* out = (float*)d_out;

    cudaFuncSetAttribute(lstm_seq8, cudaFuncAttributeMaxDynamicSharedMemorySize, SMEM_BYTES);

    xpre_mma<<<dim3(16, 256), 256>>>(x, Wx, bias);
    lstm_seq8<<<128, NTHR, SMEM_BYTES>>>(h0, c0, Wh, out);
}